// round 9
// baseline (speedup 1.0000x reference)
#include <cuda_runtime.h>
#include <math.h>

#define KK 128
#define NNODES 2048
#define DD 512
#define NSPLIT 4

__device__ float g_p1[NSPLIT * KK * DD];   // split-K partials of ctx @ Wq^T
__device__ float g_p2[NSPLIT * KK * DD];   // split-K partials of cq @ Wk
__device__ float g_compat[KK * NNODES];    // masked exp(tanh(clip(dot))/sqrt(D))
__device__ float g_wsum[KK * 64];          // per-chunk partial row sums
__device__ int   g_cnt[KK];                // per-row arrival counters (self-resetting)
__device__ int   g_mask_i32;

// ---------------------------------------------------------------------------
// Split-K projection GEMMs. Grid 512 = 16 ntiles(32) x 8 ktiles(16) x 4 splits.
//   STAGE1==false: A = ctx, B = Wq (NT) -> g_p1[split]
//   STAGE1==true : A = sum_s g_p1[s], B = Wk (NN) -> g_p2[split]
// Stage-1 block 0 also probes mask dtype (512 words all in {0,1} => int32).
// ---------------------------------------------------------------------------
template<bool STAGE1>
__global__ void __launch_bounds__(256) proj_gemm_sk(const float* __restrict__ Ain,
                                                    const float* __restrict__ B,
                                                    const int* __restrict__ m32) {
    __shared__ float As[16][129];
    __shared__ float Bs[32][129];

    const int t    = threadIdx.x;
    const int lane = t & 31;
    const int w    = t >> 5;
    const int bx   = blockIdx.x;
    const int n0   = (bx & 15) * 32;
    const int kt   = ((bx >> 4) & 7) * 16;
    const int sp   = bx >> 7;
    const int mt   = sp * 128;
    const int k0   = kt + 2 * w;

    if (!STAGE1 && bx == 0) {
        int v0 = m32[t], v1 = m32[t + 256];
        bool bad = ((v0 != 0 && v0 != 1) || (v1 != 0 && v1 != 1));
        bool any = __syncthreads_or(bad);
        if (t == 0) g_mask_i32 = any ? 0 : 1;
    }

#pragma unroll
    for (int s = 0; s < 8; ++s) {
        int idx = t + s * 256;
        int r = idx >> 7, c = idx & 127;
        if (!STAGE1) {
            As[r][c] = Ain[(kt + r) * DD + mt + c];
        } else {
            int off = (kt + r) * DD + mt + c;
            As[r][c] = g_p1[off] + g_p1[KK * DD + off]
                     + g_p1[2 * KK * DD + off] + g_p1[3 * KK * DD + off];
        }
    }
#pragma unroll
    for (int s = 0; s < 16; ++s) {
        int idx = t + s * 256;
        if (!STAGE1) {                   // NT: Bs[n][m] = Wq[n0+n][mt+m]
            int n = idx >> 7, c = idx & 127;
            Bs[n][c] = B[(n0 + n) * DD + mt + c];
        } else {                         // NN: Bs[n][m] = Wk[mt+m][n0+n]
            int n = idx & 31, c = idx >> 5;
            Bs[n][c] = B[(mt + c) * DD + n0 + n];
        }
    }
    __syncthreads();

    float acc0 = 0.f, acc1 = 0.f;
#pragma unroll 8
    for (int m = 0; m < 128; ++m) {
        float b  = Bs[lane][m];
        acc0 += As[2 * w][m] * b;
        acc1 += As[2 * w + 1][m] * b;
    }

    float* Out = STAGE1 ? g_p2 : g_p1;
    Out[(sp * KK + k0    ) * DD + n0 + lane] = acc0;
    Out[(sp * KK + k0 + 1) * DD + n0 + lane] = acc1;
}

// ---------------------------------------------------------------------------
// Streaming compat + fused masked exp + per-row closure (normalize to out).
// Grid 2048 x 128 threads. Global warp g: k = g>>6, chunk = g&63.
// |v| <= tanh(10)/sqrt(512) ~ 0.0442 -> exp cannot overflow, no max-shift.
// 64th-arriving warp of each row sums the 64 partials (fixed tree) and
// rewrites the row normalized. Atomics count arrivals only -> deterministic.
// ---------------------------------------------------------------------------
__global__ void __launch_bounds__(128) compat_kernel(const float* __restrict__ node,
                                                     const void* __restrict__ maskp,
                                                     float* __restrict__ out) {
    __shared__ float part[4][32][33];

    const int lane = threadIdx.x & 31;
    const int w    = threadIdx.x >> 5;
    const int g    = blockIdx.x * 4 + w;
    const int k    = g >> 6;
    const int chunk= g & 63;
    const int i0   = chunk * 32;

    // q[k] = sum of 4 stage-2 split partials
    const float4* p2 = reinterpret_cast<const float4*>(g_p2);
    float4 q0, q1, q2, q3;
    {
        const int rs = DD / 4;
#pragma unroll
        for (int seg = 0; seg < 4; ++seg) {
            float4 a0 = p2[(0 * KK + k) * rs + seg * 32 + lane];
            float4 b0 = p2[(1 * KK + k) * rs + seg * 32 + lane];
            float4 c0 = p2[(2 * KK + k) * rs + seg * 32 + lane];
            float4 d0 = p2[(3 * KK + k) * rs + seg * 32 + lane];
            float4 q = make_float4(a0.x+b0.x+c0.x+d0.x, a0.y+b0.y+c0.y+d0.y,
                                   a0.z+b0.z+c0.z+d0.z, a0.w+b0.w+c0.w+d0.w);
            if (seg == 0) q0 = q; else if (seg == 1) q1 = q;
            else if (seg == 2) q2 = q; else q3 = q;
        }
    }

    const float4* base = reinterpret_cast<const float4*>(node)
                       + ((size_t)(k * NNODES + i0) << 7);

#pragma unroll 4
    for (int ii = 0; ii < 32; ++ii) {
        const float4* p = base + ((size_t)ii << 7);
        float4 v0 = __ldcs(p + lane);
        float4 v1 = __ldcs(p + 32 + lane);
        float4 v2 = __ldcs(p + 64 + lane);
        float4 v3 = __ldcs(p + 96 + lane);
        float a0 = v0.x * q0.x + v0.y * q0.y + v0.z * q0.z + v0.w * q0.w;
        float a1 = v1.x * q1.x + v1.y * q1.y + v1.z * q1.z + v1.w * q1.w;
        float a2 = v2.x * q2.x + v2.y * q2.y + v2.z * q2.z + v2.w * q2.w;
        float a3 = v3.x * q3.x + v3.y * q3.y + v3.z * q3.z + v3.w * q3.w;
        part[w][ii][lane] = (a0 + a1) + (a2 + a3);
    }
    __syncwarp();

    float s0 = 0.f, s1 = 0.f, s2 = 0.f, s3 = 0.f;
#pragma unroll
    for (int j = 0; j < 32; j += 4) {
        s0 += part[w][lane][j];
        s1 += part[w][lane][j + 1];
        s2 += part[w][lane][j + 2];
        s3 += part[w][lane][j + 3];
    }
    float a = (s0 + s1) + (s2 + s3);
    float c = fminf(10.f, fmaxf(-10.f, a));
    float v = tanhf(c) * 0.04419417382415922f;   // 1/sqrt(512)

    bool msk;
    if (g_mask_i32) {
        msk = reinterpret_cast<const int*>(maskp)[k * NNODES + i0 + lane] != 0;
    } else {
        msk = reinterpret_cast<const unsigned char*>(maskp)[k * NNODES + i0 + lane] != 0;
    }
    float e = msk ? 0.f : __expf(v);
    g_compat[k * NNODES + i0 + lane] = e;      // default store: keep row L2-hot

    float ws = e;
#pragma unroll
    for (int off = 16; off; off >>= 1)
        ws += __shfl_xor_sync(0xffffffffu, ws, off);
    if (lane == 0) g_wsum[k * 64 + chunk] = ws;

    // ---- arrival + closure ----
    int old = 0;
    if (lane == 0) {
        __threadfence();                       // publish g_compat + g_wsum
        old = atomicAdd(&g_cnt[k], 1);
    }
    old = __shfl_sync(0xffffffffu, old, 0);
    if (old == 63) {
        // all 64 chunks of row k published; fixed-tree sum of partials
        float s = g_wsum[k * 64 + lane] + g_wsum[k * 64 + 32 + lane];
#pragma unroll
        for (int off = 16; off; off >>= 1)
            s += __shfl_xor_sync(0xffffffffu, s, off);
        const float inv = 1.0f / s;

        const float4* c4 = reinterpret_cast<const float4*>(g_compat) + k * (NNODES / 4);
        float4* o4 = reinterpret_cast<float4*>(out) + k * (NNODES / 4);
#pragma unroll
        for (int j = 0; j < 16; ++j) {
            float4 x = c4[j * 32 + lane];
            o4[j * 32 + lane] = make_float4(x.x * inv, x.y * inv, x.z * inv, x.w * inv);
        }
        if (lane == 0) g_cnt[k] = 0;           // reset for next graph replay
    }
}

extern "C" void kernel_launch(void* const* d_in, const int* in_sizes, int n_in,
                              void* d_out, int out_size) {
    const float* ctx  = (const float*)d_in[0];
    const float* node = (const float*)d_in[1];
    const void*  mask = d_in[2];
    const float* Wq   = (const float*)d_in[3];
    const float* Wk   = (const float*)d_in[4];
    float* out = (float*)d_out;
    (void)in_sizes; (void)n_in; (void)out_size;

    proj_gemm_sk<false><<<512, 256>>>(ctx, Wq, (const int*)mask);  // g_p1
    proj_gemm_sk<true ><<<512, 256>>>(nullptr, Wk, nullptr);       // g_p2
    compat_kernel<<<KK * 16, 128>>>(node, mask, out);              // fused closure
}

// round 10
// speedup vs baseline: 1.0798x; 1.0798x over previous
#include <cuda_runtime.h>
#include <math.h>

#define KK 128
#define NNODES 2048
#define DD 512
#define NSPLIT 4

__device__ float g_p1[NSPLIT * KK * DD];   // split-K partials of ctx @ Wq^T
__device__ float g_p2[NSPLIT * KK * DD];   // split-K partials of cq @ Wk
__device__ float g_compat[KK * NNODES];    // masked exp(tanh(clip(dot))/sqrt(D))
__device__ float g_wsum[KK * 64];          // per-chunk partial row sums
__device__ int   g_mask_i32;

// ---------------------------------------------------------------------------
// Register-tiled split-K projection GEMMs.
// Out[128,512] partials. Grid 128 = 8 ntiles(64) x 4 ktiles(32) x 4 splits.
// Block 128 threads; thread = (kq 0..7, nq 0..15) owns 4k x 4n outputs.
//   STAGE1==false: A = ctx, B = Wq (NT): out[k,n] = sum_m A[k,m]*Wq[n,m]
//                  Bs stored [n][m] (natural copy of Wq rows).
//   STAGE1==true : A = sum_s g_p1[s], B = Wk (NN): out[k,n] = sum_m A[k,m]*Wk[m,n]
//                  Bs stored [m][n] (natural copy of Wk rows).
// Inner 4-m group: 4+4 LDS.128 + 64 FFMA.
// Stage-1 block 0 also probes mask dtype (512 words all in {0,1} => int32).
// ---------------------------------------------------------------------------
template<bool STAGE1>
__global__ void __launch_bounds__(128) proj_gemm_rt(const float* __restrict__ Ain,
                                                    const float* __restrict__ B,
                                                    const int* __restrict__ m32) {
    __shared__ float As[32][132];                 // [k][m], pad 132 (16B-aligned rows)
    __shared__ float BsA[STAGE1 ? 1 : 64][STAGE1 ? 1 : 132];  // stage1: [n][m]
    __shared__ float BsB[STAGE1 ? 128 : 1][STAGE1 ? 68 : 1];  // stage2: [m][n]

    const int t   = threadIdx.x;
    const int bx  = blockIdx.x;
    const int nt  = (bx & 7) * 64;
    const int ktb = ((bx >> 3) & 3) * 32;
    const int sp  = bx >> 5;
    const int mt  = sp * 128;
    const int kq  = t >> 4;                       // 0..7  -> k = ktb + 4*kq + i
    const int nq  = t & 15;                       // 0..15 -> n = nt + 4*nq + j

    if (!STAGE1 && bx == 0) {
        int v0 = m32[t], v1 = m32[t + 128], v2 = m32[t + 256], v3 = m32[t + 384];
        bool bad = (v0 | v1 | v2 | v3) >> 1;      // any value outside {0,1}
        bool any = __syncthreads_or(bad);
        if (t == 0) g_mask_i32 = any ? 0 : 1;
    }

    // ---- As: 32 x 128 floats (8 float4/thread), coalesced ----
#pragma unroll
    for (int s = 0; s < 8; ++s) {
        int idx = t + s * 128;                    // 0..1023 float4
        int r = idx >> 5, c4 = idx & 31;
        if (!STAGE1) {
            *reinterpret_cast<float4*>(&As[r][c4 * 4]) =
                *reinterpret_cast<const float4*>(Ain + (ktb + r) * DD + mt + c4 * 4);
        } else {
            const int off = (ktb + r) * DD + mt + c4 * 4;
            float4 a = *reinterpret_cast<const float4*>(g_p1 + off);
            float4 b = *reinterpret_cast<const float4*>(g_p1 + KK * DD + off);
            float4 c = *reinterpret_cast<const float4*>(g_p1 + 2 * KK * DD + off);
            float4 d = *reinterpret_cast<const float4*>(g_p1 + 3 * KK * DD + off);
            *reinterpret_cast<float4*>(&As[r][c4 * 4]) =
                make_float4(a.x+b.x+c.x+d.x, a.y+b.y+c.y+d.y,
                            a.z+b.z+c.z+d.z, a.w+b.w+c.w+d.w);
        }
    }
    // ---- Bs: 8192 floats (16 float4/thread), coalesced natural copies ----
#pragma unroll
    for (int s = 0; s < 16; ++s) {
        int idx = t + s * 128;                    // 0..2047 float4
        if (!STAGE1) {                            // Bs[n][m] = Wq[nt+n][mt+m]
            int n = idx >> 5, c4 = idx & 31;
            *reinterpret_cast<float4*>(&BsA[n][c4 * 4]) =
                *reinterpret_cast<const float4*>(B + (nt + n) * DD + mt + c4 * 4);
        } else {                                  // Bs[m][n] = Wk[mt+m][nt+n]
            int m = idx >> 4, c4 = idx & 15;
            *reinterpret_cast<float4*>(&BsB[m][c4 * 4]) =
                *reinterpret_cast<const float4*>(B + (mt + m) * DD + nt + c4 * 4);
        }
    }
    __syncthreads();

    float acc[4][4];
#pragma unroll
    for (int i = 0; i < 4; ++i)
#pragma unroll
        for (int j = 0; j < 4; ++j) acc[i][j] = 0.f;

#pragma unroll 4
    for (int mg = 0; mg < 32; ++mg) {
        float4 a0 = *reinterpret_cast<const float4*>(&As[4 * kq + 0][4 * mg]);
        float4 a1 = *reinterpret_cast<const float4*>(&As[4 * kq + 1][4 * mg]);
        float4 a2 = *reinterpret_cast<const float4*>(&As[4 * kq + 2][4 * mg]);
        float4 a3 = *reinterpret_cast<const float4*>(&As[4 * kq + 3][4 * mg]);
        float4 av[4] = {a0, a1, a2, a3};
        if (!STAGE1) {
            // b[j] = Wq[n+j][m..m+3]  -> acc[i][j] += dot4(a[i], b[j])
            float4 b0 = *reinterpret_cast<const float4*>(&BsA[4 * nq + 0][4 * mg]);
            float4 b1 = *reinterpret_cast<const float4*>(&BsA[4 * nq + 1][4 * mg]);
            float4 b2 = *reinterpret_cast<const float4*>(&BsA[4 * nq + 2][4 * mg]);
            float4 b3 = *reinterpret_cast<const float4*>(&BsA[4 * nq + 3][4 * mg]);
            float4 bv[4] = {b0, b1, b2, b3};
#pragma unroll
            for (int i = 0; i < 4; ++i)
#pragma unroll
                for (int j = 0; j < 4; ++j)
                    acc[i][j] += av[i].x * bv[j].x + av[i].y * bv[j].y
                               + av[i].z * bv[j].z + av[i].w * bv[j].w;
        } else {
            // b[r] = Wk[m+r][n..n+3]  -> acc[i][j] += sum_r a[i].r * b[r].j
            float4 b0 = *reinterpret_cast<const float4*>(&BsB[4 * mg + 0][4 * nq]);
            float4 b1 = *reinterpret_cast<const float4*>(&BsB[4 * mg + 1][4 * nq]);
            float4 b2 = *reinterpret_cast<const float4*>(&BsB[4 * mg + 2][4 * nq]);
            float4 b3 = *reinterpret_cast<const float4*>(&BsB[4 * mg + 3][4 * nq]);
#pragma unroll
            for (int i = 0; i < 4; ++i) {
                acc[i][0] += av[i].x * b0.x + av[i].y * b1.x + av[i].z * b2.x + av[i].w * b3.x;
                acc[i][1] += av[i].x * b0.y + av[i].y * b1.y + av[i].z * b2.y + av[i].w * b3.y;
                acc[i][2] += av[i].x * b0.z + av[i].y * b1.z + av[i].z * b2.z + av[i].w * b3.z;
                acc[i][3] += av[i].x * b0.w + av[i].y * b1.w + av[i].z * b2.w + av[i].w * b3.w;
            }
        }
    }

    float* Out = (STAGE1 ? g_p2 : g_p1) + (size_t)sp * KK * DD;
#pragma unroll
    for (int i = 0; i < 4; ++i) {
        int k = ktb + 4 * kq + i;
        *reinterpret_cast<float4*>(Out + k * DD + nt + 4 * nq) =
            make_float4(acc[i][0], acc[i][1], acc[i][2], acc[i][3]);
    }
}

// ---------------------------------------------------------------------------
// Streaming compat + fused masked exp + per-warp row-sum partial (R8 version).
// Grid 2048 x 128 threads. Global warp g: k = g>>6, chunk = g&63, i0 = chunk*32.
// |v| <= tanh(10)/sqrt(512) ~ 0.0442 -> exp cannot overflow, no max-shift.
// ---------------------------------------------------------------------------
__global__ void __launch_bounds__(128) compat_kernel(const float* __restrict__ node,
                                                     const void* __restrict__ maskp) {
    __shared__ float part[4][32][33];

    const int lane = threadIdx.x & 31;
    const int w    = threadIdx.x >> 5;
    const int g    = blockIdx.x * 4 + w;
    const int k    = g >> 6;
    const int chunk= g & 63;
    const int i0   = chunk * 32;

    // q[k] = sum of 4 stage-2 split partials
    const float4* p2 = reinterpret_cast<const float4*>(g_p2);
    float4 q0, q1, q2, q3;
    {
        const int rs = DD / 4;
#pragma unroll
        for (int seg = 0; seg < 4; ++seg) {
            float4 a0 = p2[(0 * KK + k) * rs + seg * 32 + lane];
            float4 b0 = p2[(1 * KK + k) * rs + seg * 32 + lane];
            float4 c0 = p2[(2 * KK + k) * rs + seg * 32 + lane];
            float4 d0 = p2[(3 * KK + k) * rs + seg * 32 + lane];
            float4 q = make_float4(a0.x+b0.x+c0.x+d0.x, a0.y+b0.y+c0.y+d0.y,
                                   a0.z+b0.z+c0.z+d0.z, a0.w+b0.w+c0.w+d0.w);
            if (seg == 0) q0 = q; else if (seg == 1) q1 = q;
            else if (seg == 2) q2 = q; else q3 = q;
        }
    }

    const float4* base = reinterpret_cast<const float4*>(node)
                       + ((size_t)(k * NNODES + i0) << 7);

#pragma unroll 4
    for (int ii = 0; ii < 32; ++ii) {
        const float4* p = base + ((size_t)ii << 7);
        float4 v0 = __ldcs(p + lane);
        float4 v1 = __ldcs(p + 32 + lane);
        float4 v2 = __ldcs(p + 64 + lane);
        float4 v3 = __ldcs(p + 96 + lane);
        float a0 = v0.x * q0.x + v0.y * q0.y + v0.z * q0.z + v0.w * q0.w;
        float a1 = v1.x * q1.x + v1.y * q1.y + v1.z * q1.z + v1.w * q1.w;
        float a2 = v2.x * q2.x + v2.y * q2.y + v2.z * q2.z + v2.w * q2.w;
        float a3 = v3.x * q3.x + v3.y * q3.y + v3.z * q3.z + v3.w * q3.w;
        part[w][ii][lane] = (a0 + a1) + (a2 + a3);
    }
    __syncwarp();

    float s0 = 0.f, s1 = 0.f, s2 = 0.f, s3 = 0.f;
#pragma unroll
    for (int j = 0; j < 32; j += 4) {
        s0 += part[w][lane][j];
        s1 += part[w][lane][j + 1];
        s2 += part[w][lane][j + 2];
        s3 += part[w][lane][j + 3];
    }
    float a = (s0 + s1) + (s2 + s3);
    float c = fminf(10.f, fmaxf(-10.f, a));
    float v = tanhf(c) * 0.04419417382415922f;   // 1/sqrt(512)

    bool msk;
    if (g_mask_i32) {
        msk = reinterpret_cast<const int*>(maskp)[k * NNODES + i0 + lane] != 0;
    } else {
        msk = reinterpret_cast<const unsigned char*>(maskp)[k * NNODES + i0 + lane] != 0;
    }
    float e = msk ? 0.f : __expf(v);
    g_compat[k * NNODES + i0 + lane] = e;

    float ws = e;
#pragma unroll
    for (int off = 16; off; off >>= 1)
        ws += __shfl_xor_sync(0xffffffffu, ws, off);
    if (lane == 0) g_wsum[k * 64 + chunk] = ws;
}

// ---------------------------------------------------------------------------
// Normalize: grid 256 (2 blocks/row) x 256 threads.
// ---------------------------------------------------------------------------
__global__ void __launch_bounds__(256) norm_kernel(float* __restrict__ out) {
    __shared__ float s[64];
    const int b = blockIdx.x;
    const int k = b >> 1;
    const int t = threadIdx.x;

    if (t < 64) s[t] = g_wsum[k * 64 + t];
    __syncthreads();
#pragma unroll
    for (int st = 32; st; st >>= 1) {
        if (t < st) s[t] += s[t + st];
        __syncthreads();
    }
    const float inv = 1.0f / s[0];

    const int base4 = (k * NNODES + (b & 1) * 1024) / 4;
    const float4* c4 = reinterpret_cast<const float4*>(g_compat);
    float4* o4 = reinterpret_cast<float4*>(out);
    float4 v = c4[base4 + t];
    o4[base4 + t] = make_float4(v.x * inv, v.y * inv, v.z * inv, v.w * inv);
}

extern "C" void kernel_launch(void* const* d_in, const int* in_sizes, int n_in,
                              void* d_out, int out_size) {
    const float* ctx  = (const float*)d_in[0];
    const float* node = (const float*)d_in[1];
    const void*  mask = d_in[2];
    const float* Wq   = (const float*)d_in[3];
    const float* Wk   = (const float*)d_in[4];
    float* out = (float*)d_out;
    (void)in_sizes; (void)n_in; (void)out_size;

    proj_gemm_rt<false><<<128, 128>>>(ctx, Wq, (const int*)mask);  // g_p1
    proj_gemm_rt<true ><<<128, 128>>>(nullptr, Wk, nullptr);       // g_p2
    compat_kernel<<<KK * 16, 128>>>(node, mask);                   // exp + partials
    norm_kernel<<<256, 256>>>(out);                                // row-normalize
}